// round 14
// baseline (speedup 1.0000x reference)
#include <cuda_runtime.h>
#include <cuda_bf16.h>
#include <cstdint>

#define T_SEQ   4096
#define D_MODEL 1024
#define NH      16
#define NKV     4
#define HD      64
#define QL      512
#define KVL     256
#define TRI_ENT 8519680                 // 2080 tile-pairs * 4096 entries per head

// ---------------- scratch (device globals; all f32, values bf16-rounded) -----
static __device__ float g_qlat_raw[T_SEQ * QL];
static __device__ float g_qlat    [T_SEQ * QL];
static __device__ float g_q       [T_SEQ * NH * HD];
static __device__ float g_q_ro    [T_SEQ * NH * HD];
static __device__ float g_kvraw   [T_SEQ * KVL];
static __device__ float g_kvlat   [T_SEQ * KVL];
static __device__ float g_k       [T_SEQ * NKV * HD];
static __device__ float g_k_ro    [T_SEQ * NKV * HD];
static __device__ float g_v       [T_SEQ * NKV * HD];
static __device__ float g_attn    [T_SEQ * D_MODEL];

static __device__ __nv_bfloat16 g_scores[(size_t)NH * TRI_ENT];

// ---------------- helpers -----------------------------------------------------
__device__ __forceinline__ float bf16r(float x) {
    return __bfloat162float(__float2bfloat16(x));
}

typedef unsigned long long u64;

__device__ __forceinline__ u64 pack2(float lo, float hi) {
    u64 r;
    asm("mov.b64 %0, {%1, %2};" : "=l"(r) : "f"(lo), "f"(hi));
    return r;
}
__device__ __forceinline__ void unpack2(u64 v, float& lo, float& hi) {
    asm("mov.b64 {%0, %1}, %2;" : "=f"(lo), "=f"(hi) : "l"(v));
}
__device__ __forceinline__ u64 d2u(double d) {
    return (u64)__double_as_longlong(d);
}
__device__ __forceinline__ u64 fma2(u64 a, u64 b, u64 c) {
    u64 d;
    asm("fma.rn.f32x2 %0, %1, %2, %3;" : "=l"(d) : "l"(a), "l"(b), "l"(c));
    return d;
}

// Deterministic ~1-ulp exp, fmaf-only (identical since round 7).
__device__ __forceinline__ float exp_acc(float x) {
    x = fmaxf(x, -87.0f);
    float n = rintf(x * 1.44269504088896340736f);
    float r = fmaf(n, -0.693145751953125f, x);
    r = fmaf(n, -1.42860677e-06f, r);
    float p = 1.9841269841e-04f;
    p = fmaf(p, r, 1.3888888889e-03f);
    p = fmaf(p, r, 8.3333333333e-03f);
    p = fmaf(p, r, 4.1666666667e-02f);
    p = fmaf(p, r, 1.6666666667e-01f);
    p = fmaf(p, r, 0.5f);
    p = fmaf(p, r, 1.0f);
    p = fmaf(p, r, 1.0f);
    int in = (int)n;
    return p * __int_as_float((in + 127) << 23);
}

// ---------------- GEMM body: 64x64 tile, BK=32, FFMA2 + prefetch --------------
__device__ __forceinline__ void gemm_body(const float* __restrict__ A,
                                          const float* __restrict__ B,
                                          float* __restrict__ C,
                                          int N, int K, int row0, int col0,
                                          float (*As)[68], float (*Bs)[68]) {
    const int tid = threadIdx.x;
    const int tx = tid & 15;
    const int ty = tid >> 4;

    const int a_row  = tid & 63;
    const int a_half = tid >> 6;
    const int b_row  = tid >> 2;
    const int b_col  = (tid & 3) * 16;

    const int nkt = K >> 5;
    float a_st[16], b_st[16];

    auto ldg_tile = [&](int kt) {
        const float* ap = A + (size_t)(row0 + a_row) * K + kt * 32 + a_half * 16;
#pragma unroll
        for (int u = 0; u < 4; u++)
            *(float4*)&a_st[u * 4] = ((const float4*)ap)[u];
        const float* bp = B + (size_t)(kt * 32 + b_row) * N + col0 + b_col;
#pragma unroll
        for (int u = 0; u < 4; u++)
            *(float4*)&b_st[u * 4] = ((const float4*)bp)[u];
    };
    auto sts_tile = [&]() {
#pragma unroll
        for (int u = 0; u < 16; u++)
            As[a_half * 16 + u][a_row] = a_st[u];
#pragma unroll
        for (int u = 0; u < 4; u++)
            *(float4*)&Bs[b_row][b_col + u * 4] = *(float4*)&b_st[u * 4];
    };

    u64 acc2[4][4];
#pragma unroll
    for (int p = 0; p < 4; p++)
#pragma unroll
        for (int j = 0; j < 4; j++) acc2[p][j] = 0ull;

    ldg_tile(0);
    sts_tile();
    __syncthreads();

    for (int kt = 0; kt < nkt; kt++) {
        if (kt + 1 < nkt) ldg_tile(kt + 1);

#pragma unroll 4
        for (int kk = 0; kk < 32; kk++) {
            float4 bf = *(const float4*)&Bs[kk][tx * 4];
            u64 b0 = pack2(bf.x, bf.x);
            u64 b1 = pack2(bf.y, bf.y);
            u64 b2 = pack2(bf.z, bf.z);
            u64 b3 = pack2(bf.w, bf.w);
            double2 a01 = *(const double2*)&As[kk][ty * 8];
            double2 a23 = *(const double2*)&As[kk][ty * 8 + 4];
            u64 ap_[4] = { d2u(a01.x), d2u(a01.y), d2u(a23.x), d2u(a23.y) };
#pragma unroll
            for (int p = 0; p < 4; p++) {
                acc2[p][0] = fma2(ap_[p], b0, acc2[p][0]);
                acc2[p][1] = fma2(ap_[p], b1, acc2[p][1]);
                acc2[p][2] = fma2(ap_[p], b2, acc2[p][2]);
                acc2[p][3] = fma2(ap_[p], b3, acc2[p][3]);
            }
        }

        if (kt + 1 < nkt) {
            __syncthreads();
            sts_tile();
            __syncthreads();
        }
    }

#pragma unroll
    for (int p = 0; p < 4; p++) {
        float lo0, hi0, lo1, hi1, lo2, hi2, lo3, hi3;
        unpack2(acc2[p][0], lo0, hi0);
        unpack2(acc2[p][1], lo1, hi1);
        unpack2(acc2[p][2], lo2, hi2);
        unpack2(acc2[p][3], lo3, hi3);
        float4 ve = make_float4(bf16r(lo0), bf16r(lo1), bf16r(lo2), bf16r(lo3));
        float4 vo = make_float4(bf16r(hi0), bf16r(hi1), bf16r(hi2), bf16r(hi3));
        *(float4*)&C[(size_t)(row0 + ty * 8 + 2 * p)     * N + col0 + tx * 4] = ve;
        *(float4*)&C[(size_t)(row0 + ty * 8 + 2 * p + 1) * N + col0 + tx * 4] = vo;
    }
}

__global__ void __launch_bounds__(128, 4)
gemm_ffma2(const float* __restrict__ A,
           const float* __restrict__ B,
           float* __restrict__ C,
           int M, int N, int K) {
    __shared__ float As[32][68];
    __shared__ float Bs[32][68];
    gemm_body(A, B, C, N, K, blockIdx.y * 64, blockIdx.x * 64, As, Bs);
}

// merged dispatch: qlat@w_uq (1024 blocks), kvlat@w_uk (256), kvlat@w_uv (256)
__global__ void __launch_bounds__(128, 4)
gemm3_kernel(const float* __restrict__ qlat, const float* __restrict__ w_uq,
             float* __restrict__ qb,
             const float* __restrict__ kvlat, const float* __restrict__ w_uk,
             float* __restrict__ kb, const float* __restrict__ w_uv,
             float* __restrict__ vb) {
    __shared__ float As[32][68];
    __shared__ float Bs[32][68];
    int bx = blockIdx.x;
    if (bx < 1024) {
        gemm_body(qlat, w_uq, qb, NH * HD, QL, (bx >> 4) * 64, (bx & 15) * 64, As, Bs);
    } else if (bx < 1280) {
        int b = bx - 1024;
        gemm_body(kvlat, w_uk, kb, NKV * HD, KVL, (b >> 2) * 64, (b & 3) * 64, As, Bs);
    } else {
        int b = bx - 1280;
        gemm_body(kvlat, w_uv, vb, NKV * HD, KVL, (b >> 2) * 64, (b & 3) * 64, As, Bs);
    }
}

// ---------------- RMSNorm merged (same FP ops per row) -------------------------
__global__ void rmsnorm_both(const float* __restrict__ inq,
                             const float* __restrict__ scq,
                             float* __restrict__ outq,
                             const float* __restrict__ inkv,
                             const float* __restrict__ sckv,
                             float* __restrict__ outkv) {
    const float* in;
    const float* scale;
    float* out;
    int cols;
    if (blockIdx.y == 0) { in = inq;  scale = scq;  out = outq;  cols = QL;  }
    else                 { in = inkv; scale = sckv; out = outkv; cols = KVL; }

    const int row = blockIdx.x;
    const int tid = threadIdx.x;
    const float* x = in + (size_t)row * cols;
    float* y = out + (size_t)row * cols;

    __shared__ float red[256];
    float s = 0.0f;
    for (int c = tid; c < cols; c += 256) {
        float v = x[c];
        s = fmaf(v, v, s);
    }
    red[tid] = s;
    __syncthreads();
    for (int off = 128; off > 0; off >>= 1) {
        if (tid < off) red[tid] += red[tid + off];
        __syncthreads();
    }
    float rms = __fsqrt_rn(red[0] / (float)cols + 1e-6f);
    for (int c = tid; c < cols; c += 256)
        y[c] = bf16r(__fdiv_rn(x[c], rms) * scale[c]);
}

// ---------------- RoPE merged (same FP ops per element) ------------------------
__global__ void rope_both(const float* __restrict__ qin,  float* __restrict__ qout,
                          const float* __restrict__ kin,  float* __restrict__ kout,
                          const float* __restrict__ sin_t,
                          const float* __restrict__ cos_t) {
    int idx = blockIdx.x * blockDim.x + threadIdx.x;
    const int nq = T_SEQ * NH * HD;
    const int nk = T_SEQ * NKV * HD;
    if (idx >= nq + nk) return;

    const float* in;
    float* out;
    int heads, li;
    if (idx < nq) { in = qin; out = qout; heads = NH;  li = idx; }
    else          { in = kin; out = kout; heads = NKV; li = idx - nq; }

    int d = li & 63;
    int t = (li >> 6) / heads;
    float xv = in[li];
    float rot = (d < 32) ? -in[li + 32] : in[li - 32];
    float r1 = bf16r(xv * cos_t[t * HD + d]);
    float r2 = bf16r(rot * sin_t[t * HD + d]);
    out[li] = bf16r(r1 + r2);
}

// ---------------- causal attention (R13 + K/V register prefetch) ---------------
__global__ void __launch_bounds__(128, 4)
attn_kernel(const float* __restrict__ Q,
            const float* __restrict__ Kc,
            const float* __restrict__ Vc,
            float* __restrict__ O,
            __nv_bfloat16* __restrict__ Sc) {
    __shared__ float QP[64][68];   // pass1: Qs[i][row]; pass3: PsT[j][row]
    __shared__ float KV[64][68];   // pass1: Ks[i][key]; pass3: Vs[j][dim]
    __shared__ float m_s[64];
    __shared__ float l_s[64];

    const int qtile = (int)gridDim.x - 1 - (int)blockIdx.x;
    const int h = blockIdx.y;
    const int hk = h >> 2;
    const int tid = threadIdx.x;
    const size_t sbase = (size_t)h * TRI_ENT +
                         (size_t)qtile * (qtile + 1) / 2 * 4096;

    const int rg = tid >> 3;
    const int kg = tid & 7;

    {
        const int r_ld = tid >> 1, dh = tid & 1;
        const float* qp = Q + (size_t)(qtile * 64 + r_ld) * D_MODEL + h * HD + dh * 32;
        float qv[32];
#pragma unroll
        for (int u = 0; u < 8; u++)
            *(float4*)&qv[u * 4] = ((const float4*)qp)[u];
#pragma unroll
        for (int u = 0; u < 32; u++)
            QP[dh * 32 + u][r_ld] = qv[u];
    }

    float mreg[4] = { -1e30f, -1e30f, -1e30f, -1e30f };
    float kst[32];
    const int key_ld = tid >> 1, dh_ld = tid & 1;

    auto ldg_k = [&](int kt) {
        const float* kp = Kc + (size_t)(kt * 64 + key_ld) * (NKV * HD) + hk * HD + dh_ld * 32;
#pragma unroll
        for (int u = 0; u < 8; u++)
            *(float4*)&kst[u * 4] = ((const float4*)kp)[u];
    };
    auto sts_kT = [&]() {   // transposed: KV[dim][key]
#pragma unroll
        for (int u = 0; u < 32; u++)
            KV[dh_ld * 32 + u][key_ld] = kst[u];
    };
    auto ldg_v = [&](int kt) {
        const float* vp = Vc + (size_t)(kt * 64 + key_ld) * (NKV * HD) + hk * HD + dh_ld * 32;
#pragma unroll
        for (int u = 0; u < 8; u++)
            *(float4*)&kst[u * 4] = ((const float4*)vp)[u];
    };
    auto sts_v = [&]() {    // straight: KV[key][dim]
#pragma unroll
        for (int u = 0; u < 8; u++)
            *(float4*)&KV[key_ld][dh_ld * 32 + u * 4] = *(float4*)&kst[u * 4];
    };

    // ================= pass 1: QK GEMM, store bf16 scores, exact max =========
    ldg_k(0);
    for (int kt = 0; kt <= qtile; kt++) {
        __syncthreads();           // prior tile's reads done
        sts_kT();
        __syncthreads();
        if (kt + 1 <= qtile) ldg_k(kt + 1);   // overlap next LDG with compute

        u64 alo[4][4], ahi[4][4];
#pragma unroll
        for (int a = 0; a < 4; a++)
#pragma unroll
            for (int b = 0; b < 4; b++) { alo[a][b] = 0ull; ahi[a][b] = 0ull; }

#pragma unroll 8
        for (int i = 0; i < 32; i++) {
            float4 qv = *(const float4*)&QP[i][rg * 4];
            double2 ka = *(const double2*)&KV[i][kg * 8];
            double2 kb = *(const double2*)&KV[i][kg * 8 + 4];
            u64 kp_[4] = { d2u(ka.x), d2u(ka.y), d2u(kb.x), d2u(kb.y) };
            u64 q_[4] = { pack2(qv.x, qv.x), pack2(qv.y, qv.y),
                          pack2(qv.z, qv.z), pack2(qv.w, qv.w) };
#pragma unroll
            for (int a = 0; a < 4; a++)
#pragma unroll
                for (int b = 0; b < 4; b++)
                    alo[a][b] = fma2(q_[a], kp_[b], alo[a][b]);
        }
#pragma unroll 8
        for (int i = 32; i < 64; i++) {
            float4 qv = *(const float4*)&QP[i][rg * 4];
            double2 ka = *(const double2*)&KV[i][kg * 8];
            double2 kb = *(const double2*)&KV[i][kg * 8 + 4];
            u64 kp_[4] = { d2u(ka.x), d2u(ka.y), d2u(kb.x), d2u(kb.y) };
            u64 q_[4] = { pack2(qv.x, qv.x), pack2(qv.y, qv.y),
                          pack2(qv.z, qv.z), pack2(qv.w, qv.w) };
#pragma unroll
            for (int a = 0; a < 4; a++)
#pragma unroll
                for (int b = 0; b < 4; b++)
                    ahi[a][b] = fma2(q_[a], kp_[b], ahi[a][b]);
        }

        float scv[8][4];
#pragma unroll
        for (int b = 0; b < 4; b++)
#pragma unroll
            for (int a = 0; a < 4; a++) {
                float l0, l1, h0, h1;
                unpack2(alo[a][b], l0, l1);
                unpack2(ahi[a][b], h0, h1);
                scv[b * 2][a]     = l0 + h0;
                scv[b * 2 + 1][a] = l1 + h1;
            }
#pragma unroll
        for (int jj = 0; jj < 8; jj++) {
            int j = kg * 8 + jj;
            int gj = kt * 64 + j;
            __nv_bfloat162 pa = __floats2bfloat162_rn(scv[jj][0], scv[jj][1]);
            __nv_bfloat162 pb = __floats2bfloat162_rn(scv[jj][2], scv[jj][3]);
            uint2 st;
            st.x = *(unsigned int*)&pa;
            st.y = *(unsigned int*)&pb;
            *(uint2*)(Sc + sbase + (size_t)gj * 64 + rg * 4) = st;
#pragma unroll
            for (int a = 0; a < 4; a++) {
                float s = bf16r(scv[jj][a]) * 0.125f;
                int trow = qtile * 64 + rg * 4 + a;
                if (gj <= trow) mreg[a] = fmaxf(mreg[a], s);
            }
        }
    }

#pragma unroll
    for (int a = 0; a < 4; a++) {
        float v = mreg[a];
        v = fmaxf(v, __shfl_xor_sync(0xffffffffu, v, 1));
        v = fmaxf(v, __shfl_xor_sync(0xffffffffu, v, 2));
        v = fmaxf(v, __shfl_xor_sync(0xffffffffu, v, 4));
        mreg[a] = v;
    }
    if (kg == 0) {
#pragma unroll
        for (int a = 0; a < 4; a++) m_s[rg * 4 + a] = mreg[a];
    }
    __syncthreads();

    // ================= pass 2: l chain (byte-identical structure to R10) =====
    {
        const int r2 = tid >> 1, hf2 = tid & 1;
        const unsigned pair_mask = 0x3u << ((tid & 31) & ~1);
        const float m = m_s[r2];
        float l = 0.0f;
        for (int kt = 0; kt <= qtile; kt++) {
            const int jmax = (kt == qtile) ? r2 : 63;
            int j = 0;
            for (; j + 1 <= jmax; j += 2) {
                int jm = j + hf2;
                float s = __bfloat162float(Sc[sbase + (size_t)(kt * 64 + jm) * 64 + r2]) * 0.125f;
                float e = exp_acc(s - m);
                float eo = __shfl_xor_sync(pair_mask, e, 1);
                float e_even = hf2 ? eo : e;
                float e_odd  = hf2 ? e  : eo;
                l += e_even;
                l += e_odd;
            }
            if (j <= jmax) {
                float s = __bfloat162float(Sc[sbase + (size_t)(kt * 64 + j) * 64 + r2]) * 0.125f;
                l += exp_acc(s - m);
            }
        }
        if (hf2 == 0) l_s[r2] = l;
    }
    __syncthreads();

    // ================= pass 3: probs (PsT[j][row]) + PV GEMM =================
    u64 o2[4][4];
#pragma unroll
    for (int a = 0; a < 4; a++)
#pragma unroll
        for (int b = 0; b < 4; b++) o2[a][b] = 0ull;

    const int pj = tid & 63, ph = tid >> 6;

    ldg_v(0);
    for (int kt = 0; kt <= qtile; kt++) {
        __syncthreads();
        sts_v();
        // probs: thread owns key pj, rows ph*32..+31 -> PsT[pj][row]
        {
            const unsigned int* spw = (const unsigned int*)
                (Sc + sbase + (size_t)(kt * 64 + pj) * 64 + ph * 32);
            const int gj = kt * 64 + pj;
#pragma unroll
            for (int q4 = 0; q4 < 4; q4++) {
                uint4 wv = ((const uint4*)spw)[q4];
                unsigned int ws[4] = { wv.x, wv.y, wv.z, wv.w };
                float pv[8];
#pragma unroll
                for (int wi = 0; wi < 4; wi++) {
                    unsigned int word = ws[wi];
                    int rr0 = wi * 2;
#pragma unroll
                    for (int e = 0; e < 2; e++) {
                        int row = ph * 32 + q4 * 8 + rr0 + e;
                        float p = 0.0f;
                        if (gj <= qtile * 64 + row) {
                            float sv = __uint_as_float(e ? (word & 0xffff0000u)
                                                         : (word << 16));
                            float s = sv * 0.125f;
                            p = bf16r(__fdiv_rn(exp_acc(s - m_s[row]), l_s[row]));
                        }
                        pv[rr0 + e] = p;
                    }
                }
                *(float4*)&QP[pj][ph * 32 + q4 * 8]     = *(float4*)&pv[0];
                *(float4*)&QP[pj][ph * 32 + q4 * 8 + 4] = *(float4*)&pv[4];
            }
        }
        __syncthreads();
        if (kt + 1 <= qtile) ldg_v(kt + 1);   // overlap next LDG with PV compute

#pragma unroll 2
        for (int j = 0; j < 64; j++) {
            float4 pf = *(const float4*)&QP[j][rg * 4];
            u64 pp[4] = { pack2(pf.x, pf.x), pack2(pf.y, pf.y),
                          pack2(pf.z, pf.z), pack2(pf.w, pf.w) };
            double2 va = *(const double2*)&KV[j][kg * 8];
            double2 vb = *(const double2*)&KV[j][kg * 8 + 4];
            u64 vv[4] = { d2u(va.x), d2u(va.y), d2u(vb.x), d2u(vb.y) };
#pragma unroll
            for (int a = 0; a < 4; a++)
#pragma unroll
                for (int b = 0; b < 4; b++)
                    o2[a][b] = fma2(pp[a], vv[b], o2[a][b]);
        }
    }

#pragma unroll
    for (int a = 0; a < 4; a++) {
        int trow = qtile * 64 + rg * 4 + a;
        float* op = O + (size_t)trow * D_MODEL + h * HD + kg * 8;
        float f0, f1, f2, f3, f4, f5, f6, f7;
        unpack2(o2[a][0], f0, f1);
        unpack2(o2[a][1], f2, f3);
        unpack2(o2[a][2], f4, f5);
        unpack2(o2[a][3], f6, f7);
        *(float4*)&op[0] = make_float4(bf16r(f0), bf16r(f1), bf16r(f2), bf16r(f3));
        *(float4*)&op[4] = make_float4(bf16r(f4), bf16r(f5), bf16r(f6), bf16r(f7));
    }
}

// ---------------- host launcher ----------------------------------------------
extern "C" void kernel_launch(void* const* d_in, const int* in_sizes, int n_in,
                              void* d_out, int out_size) {
    (void)out_size;

    const float *x = 0, *w_o = 0, *scale_q = 0, *scale_kv = 0;
    const float *p524[2] = {0, 0}, *p262[3] = {0, 0, 0}, *p65[2] = {0, 0};
    int n524 = 0, n262 = 0, n65 = 0;
    for (int i = 0; i < n_in; i++) {
        switch (in_sizes[i]) {
            case 4194304: x = (const float*)d_in[i]; break;
            case 1048576: w_o = (const float*)d_in[i]; break;
            case 512:     scale_q  = (const float*)d_in[i]; break;
            case 256:     scale_kv = (const float*)d_in[i]; break;
            case 524288:  if (n524 < 2) p524[n524++] = (const float*)d_in[i]; break;
            case 262144:  if (n262 < 3) p262[n262++] = (const float*)d_in[i]; break;
            case 65536:   if (n65 < 2)  p65[n65++]  = (const float*)d_in[i]; break;
            default: break;
        }
    }
    const float* w_dq  = p524[0];
    const float* w_uq  = p524[1];
    const float* sin_p = p262[0];
    const float* cos_p = p262[1];
    const float* w_dkv = p262[2];
    const float* w_uk  = p65[0];
    const float* w_uv  = p65[1];
    float* out = (float*)d_out;

    float *qlat_raw, *qlat, *qb, *q_ro, *kvraw, *kvlat, *kb, *k_ro, *vb, *attn;
    __nv_bfloat16* scores;
    cudaGetSymbolAddress((void**)&qlat_raw, g_qlat_raw);
    cudaGetSymbolAddress((void**)&qlat,     g_qlat);
    cudaGetSymbolAddress((void**)&qb,       g_q);
    cudaGetSymbolAddress((void**)&q_ro,     g_q_ro);
    cudaGetSymbolAddress((void**)&kvraw,    g_kvraw);
    cudaGetSymbolAddress((void**)&kvlat,    g_kvlat);
    cudaGetSymbolAddress((void**)&kb,       g_k);
    cudaGetSymbolAddress((void**)&k_ro,     g_k_ro);
    cudaGetSymbolAddress((void**)&vb,       g_v);
    cudaGetSymbolAddress((void**)&attn,     g_attn);
    cudaGetSymbolAddress((void**)&scores,   g_scores);

    // launch 0: x @ w_dq
    gemm_ffma2<<<dim3(QL / 64, T_SEQ / 64), 128>>>(x, w_dq, qlat_raw,
                                                   T_SEQ, QL, D_MODEL);
    // launch 1: x @ w_dkv
    gemm_ffma2<<<dim3(KVL / 64, T_SEQ / 64), 128>>>(x, w_dkv, kvraw,
                                                    T_SEQ, KVL, D_MODEL);
    // launch 2: both rmsnorms
    rmsnorm_both<<<dim3(T_SEQ, 2), 256>>>(qlat_raw, scale_q, qlat,
                                          kvraw, scale_kv, kvlat);
    // launch 3: q/k/v up-projections (merged dispatch)
    gemm3_kernel<<<1536, 128>>>(qlat, w_uq, qb, kvlat, w_uk, kb, w_uv, vb);
    // launch 4: both ropes
    {
        int total = T_SEQ * NH * HD + T_SEQ * NKV * HD;
        rope_both<<<(total + 255) / 256, 256>>>(qb, q_ro, kb, k_ro, sin_p, cos_p);
    }
    // launch 5: attention  <-- ncu profiles this one (-s 5 -c 1)
    attn_kernel<<<dim3(T_SEQ / 64, NH), 128>>>(q_ro, k_ro, vb, attn, scores);
    // launch 6: final projection
    gemm_ffma2<<<dim3(D_MODEL / 64, T_SEQ / 64), 128>>>(attn, w_o, out,
                                                        T_SEQ, D_MODEL, D_MODEL);
}

// round 15
// speedup vs baseline: 1.0067x; 1.0067x over previous
#include <cuda_runtime.h>
#include <cuda_bf16.h>
#include <cstdint>

#define T_SEQ   4096
#define D_MODEL 1024
#define NH      16
#define NKV     4
#define HD      64
#define QL      512
#define KVL     256
#define TRI_ENT 8519680                 // 2080 tile-pairs * 4096 entries per head

// ---------------- scratch (device globals; all f32, values bf16-rounded) -----
static __device__ float g_qlat_raw[T_SEQ * QL];
static __device__ float g_qlat    [T_SEQ * QL];
static __device__ float g_q_ro    [T_SEQ * NH * HD];
static __device__ float g_kvraw   [T_SEQ * KVL];
static __device__ float g_kvlat   [T_SEQ * KVL];
static __device__ float g_k_ro    [T_SEQ * NKV * HD];
static __device__ float g_v       [T_SEQ * NKV * HD];
static __device__ float g_attn    [T_SEQ * D_MODEL];

static __device__ __nv_bfloat16 g_scores[(size_t)NH * TRI_ENT];

// ---------------- helpers -----------------------------------------------------
__device__ __forceinline__ float bf16r(float x) {
    return __bfloat162float(__float2bfloat16(x));
}

typedef unsigned long long u64;

__device__ __forceinline__ u64 pack2(float lo, float hi) {
    u64 r;
    asm("mov.b64 %0, {%1, %2};" : "=l"(r) : "f"(lo), "f"(hi));
    return r;
}
__device__ __forceinline__ void unpack2(u64 v, float& lo, float& hi) {
    asm("mov.b64 {%0, %1}, %2;" : "=f"(lo), "=f"(hi) : "l"(v));
}
__device__ __forceinline__ u64 d2u(double d) {
    return (u64)__double_as_longlong(d);
}
__device__ __forceinline__ u64 fma2(u64 a, u64 b, u64 c) {
    u64 d;
    asm("fma.rn.f32x2 %0, %1, %2, %3;" : "=l"(d) : "l"(a), "l"(b), "l"(c));
    return d;
}

// Deterministic ~1-ulp exp, fmaf-only (identical since round 7).
__device__ __forceinline__ float exp_acc(float x) {
    x = fmaxf(x, -87.0f);
    float n = rintf(x * 1.44269504088896340736f);
    float r = fmaf(n, -0.693145751953125f, x);
    r = fmaf(n, -1.42860677e-06f, r);
    float p = 1.9841269841e-04f;
    p = fmaf(p, r, 1.3888888889e-03f);
    p = fmaf(p, r, 8.3333333333e-03f);
    p = fmaf(p, r, 4.1666666667e-02f);
    p = fmaf(p, r, 1.6666666667e-01f);
    p = fmaf(p, r, 0.5f);
    p = fmaf(p, r, 1.0f);
    p = fmaf(p, r, 1.0f);
    int in = (int)n;
    return p * __int_as_float((in + 127) << 23);
}

// ---------------- GEMM body: 64x64 tile, BK=32, FFMA2 + prefetch --------------
// rope=1: apply RoPE to the bf16r outputs in the epilogue (tile == one head).
__device__ __forceinline__ void gemm_body(const float* __restrict__ A,
                                          const float* __restrict__ B,
                                          float* __restrict__ C,
                                          int N, int K, int row0, int col0,
                                          float (*As)[68], float (*Bs)[68],
                                          const float* __restrict__ sin_t,
                                          const float* __restrict__ cos_t,
                                          int rope) {
    const int tid = threadIdx.x;
    const int tx = tid & 15;
    const int ty = tid >> 4;

    const int a_row  = tid & 63;
    const int a_half = tid >> 6;
    const int b_row  = tid >> 2;
    const int b_col  = (tid & 3) * 16;

    const int nkt = K >> 5;
    float a_st[16], b_st[16];

    auto ldg_tile = [&](int kt) {
        const float* ap = A + (size_t)(row0 + a_row) * K + kt * 32 + a_half * 16;
#pragma unroll
        for (int u = 0; u < 4; u++)
            *(float4*)&a_st[u * 4] = ((const float4*)ap)[u];
        const float* bp = B + (size_t)(kt * 32 + b_row) * N + col0 + b_col;
#pragma unroll
        for (int u = 0; u < 4; u++)
            *(float4*)&b_st[u * 4] = ((const float4*)bp)[u];
    };
    auto sts_tile = [&]() {
#pragma unroll
        for (int u = 0; u < 16; u++)
            As[a_half * 16 + u][a_row] = a_st[u];
#pragma unroll
        for (int u = 0; u < 4; u++)
            *(float4*)&Bs[b_row][b_col + u * 4] = *(float4*)&b_st[u * 4];
    };

    u64 acc2[4][4];
#pragma unroll
    for (int p = 0; p < 4; p++)
#pragma unroll
        for (int j = 0; j < 4; j++) acc2[p][j] = 0ull;

    ldg_tile(0);
    sts_tile();
    __syncthreads();

    for (int kt = 0; kt < nkt; kt++) {
        if (kt + 1 < nkt) ldg_tile(kt + 1);

#pragma unroll 4
        for (int kk = 0; kk < 32; kk++) {
            float4 bf = *(const float4*)&Bs[kk][tx * 4];
            u64 b0 = pack2(bf.x, bf.x);
            u64 b1 = pack2(bf.y, bf.y);
            u64 b2 = pack2(bf.z, bf.z);
            u64 b3 = pack2(bf.w, bf.w);
            double2 a01 = *(const double2*)&As[kk][ty * 8];
            double2 a23 = *(const double2*)&As[kk][ty * 8 + 4];
            u64 ap_[4] = { d2u(a01.x), d2u(a01.y), d2u(a23.x), d2u(a23.y) };
#pragma unroll
            for (int p = 0; p < 4; p++) {
                acc2[p][0] = fma2(ap_[p], b0, acc2[p][0]);
                acc2[p][1] = fma2(ap_[p], b1, acc2[p][1]);
                acc2[p][2] = fma2(ap_[p], b2, acc2[p][2]);
                acc2[p][3] = fma2(ap_[p], b3, acc2[p][3]);
            }
        }

        if (kt + 1 < nkt) {
            __syncthreads();
            sts_tile();
            __syncthreads();
        }
    }

#pragma unroll
    for (int p = 0; p < 4; p++) {
        float ve[4], vo[4];
        unpack2(acc2[p][0], ve[0], vo[0]);
        unpack2(acc2[p][1], ve[1], vo[1]);
        unpack2(acc2[p][2], ve[2], vo[2]);
        unpack2(acc2[p][3], ve[3], vo[3]);
#pragma unroll
        for (int i = 0; i < 4; i++) { ve[i] = bf16r(ve[i]); vo[i] = bf16r(vo[i]); }

        if (rope) {
            // tile covers one head: d = tx*4+i; rotate-half partner in lane tx^8
            const int te = row0 + ty * 8 + 2 * p;
            const int to = te + 1;
            float oe[4], oo[4];
#pragma unroll
            for (int i = 0; i < 4; i++) {
                float pe = __shfl_xor_sync(0xffffffffu, ve[i], 8);
                float po = __shfl_xor_sync(0xffffffffu, vo[i], 8);
                int d = tx * 4 + i;
                float re = (d < 32) ? -pe : pe;
                float ro = (d < 32) ? -po : po;
                float ce = cos_t[te * HD + d], se = sin_t[te * HD + d];
                float co = cos_t[to * HD + d], so = sin_t[to * HD + d];
                oe[i] = bf16r(bf16r(ve[i] * ce) + bf16r(re * se));
                oo[i] = bf16r(bf16r(vo[i] * co) + bf16r(ro * so));
            }
#pragma unroll
            for (int i = 0; i < 4; i++) { ve[i] = oe[i]; vo[i] = oo[i]; }
        }

        *(float4*)&C[(size_t)(row0 + ty * 8 + 2 * p)     * N + col0 + tx * 4] =
            make_float4(ve[0], ve[1], ve[2], ve[3]);
        *(float4*)&C[(size_t)(row0 + ty * 8 + 2 * p + 1) * N + col0 + tx * 4] =
            make_float4(vo[0], vo[1], vo[2], vo[3]);
    }
}

// launch 0: both down-projections (x@w_dq -> qlat_raw, x@w_dkv -> kvraw)
__global__ void __launch_bounds__(128, 4)
downproj_kernel(const float* __restrict__ x,
                const float* __restrict__ w_dq, float* __restrict__ qlat_raw,
                const float* __restrict__ w_dkv, float* __restrict__ kvraw) {
    __shared__ float As[32][68];
    __shared__ float Bs[32][68];
    int bx = blockIdx.x;
    if (bx < 512)
        gemm_body(x, w_dq, qlat_raw, QL, D_MODEL, (bx >> 3) * 64, (bx & 7) * 64,
                  As, Bs, 0, 0, 0);
    else {
        int b = bx - 512;
        gemm_body(x, w_dkv, kvraw, KVL, D_MODEL, (b >> 2) * 64, (b & 3) * 64,
                  As, Bs, 0, 0, 0);
    }
}

// launch 2: q/k up-projections WITH fused rope, v plain
__global__ void __launch_bounds__(128, 4)
gemm3_rope_kernel(const float* __restrict__ qlat, const float* __restrict__ w_uq,
                  float* __restrict__ q_ro,
                  const float* __restrict__ kvlat, const float* __restrict__ w_uk,
                  float* __restrict__ k_ro, const float* __restrict__ w_uv,
                  float* __restrict__ vb,
                  const float* __restrict__ sin_t,
                  const float* __restrict__ cos_t) {
    __shared__ float As[32][68];
    __shared__ float Bs[32][68];
    int bx = blockIdx.x;
    if (bx < 1024) {
        gemm_body(qlat, w_uq, q_ro, NH * HD, QL, (bx >> 4) * 64, (bx & 15) * 64,
                  As, Bs, sin_t, cos_t, 1);
    } else if (bx < 1280) {
        int b = bx - 1024;
        gemm_body(kvlat, w_uk, k_ro, NKV * HD, KVL, (b >> 2) * 64, (b & 3) * 64,
                  As, Bs, sin_t, cos_t, 1);
    } else {
        int b = bx - 1280;
        gemm_body(kvlat, w_uv, vb, NKV * HD, KVL, (b >> 2) * 64, (b & 3) * 64,
                  As, Bs, 0, 0, 0);
    }
}

// launch 4: final projection
__global__ void __launch_bounds__(128, 4)
gemm_wo_kernel(const float* __restrict__ A,
               const float* __restrict__ B,
               float* __restrict__ C) {
    __shared__ float As[32][68];
    __shared__ float Bs[32][68];
    gemm_body(A, B, C, D_MODEL, D_MODEL, blockIdx.y * 64, blockIdx.x * 64,
              As, Bs, 0, 0, 0);
}

// ---------------- RMSNorm merged (same FP ops per row) -------------------------
__global__ void rmsnorm_both(const float* __restrict__ inq,
                             const float* __restrict__ scq,
                             float* __restrict__ outq,
                             const float* __restrict__ inkv,
                             const float* __restrict__ sckv,
                             float* __restrict__ outkv) {
    const float* in;
    const float* scale;
    float* out;
    int cols;
    if (blockIdx.y == 0) { in = inq;  scale = scq;  out = outq;  cols = QL;  }
    else                 { in = inkv; scale = sckv; out = outkv; cols = KVL; }

    const int row = blockIdx.x;
    const int tid = threadIdx.x;
    const float* x = in + (size_t)row * cols;
    float* y = out + (size_t)row * cols;

    __shared__ float red[256];
    float s = 0.0f;
    for (int c = tid; c < cols; c += 256) {
        float v = x[c];
        s = fmaf(v, v, s);
    }
    red[tid] = s;
    __syncthreads();
    for (int off = 128; off > 0; off >>= 1) {
        if (tid < off) red[tid] += red[tid + off];
        __syncthreads();
    }
    float rms = __fsqrt_rn(red[0] / (float)cols + 1e-6f);
    for (int c = tid; c < cols; c += 256)
        y[c] = bf16r(__fdiv_rn(x[c], rms) * scale[c]);
}

// ---------------- causal attention (pass-1 K double-buffered) ------------------
__global__ void __launch_bounds__(128, 4)
attn_kernel(const float* __restrict__ Q,
            const float* __restrict__ Kc,
            const float* __restrict__ Vc,
            float* __restrict__ O,
            __nv_bfloat16* __restrict__ Sc) {
    __shared__ float QP[64][68];      // pass1: Qs[i][row]; pass3: PsT[j][row]
    __shared__ float KV[2][64][68];   // pass1: K double-buffer; pass3: KV[0]=V
    __shared__ float m_s[64];
    __shared__ float l_s[64];

    const int qtile = (int)gridDim.x - 1 - (int)blockIdx.x;
    const int h = blockIdx.y;
    const int hk = h >> 2;
    const int tid = threadIdx.x;
    const size_t sbase = (size_t)h * TRI_ENT +
                         (size_t)qtile * (qtile + 1) / 2 * 4096;

    const int rg = tid >> 3;
    const int kg = tid & 7;

    {
        const int r_ld = tid >> 1, dh = tid & 1;
        const float* qp = Q + (size_t)(qtile * 64 + r_ld) * D_MODEL + h * HD + dh * 32;
        float qv[32];
#pragma unroll
        for (int u = 0; u < 8; u++)
            *(float4*)&qv[u * 4] = ((const float4*)qp)[u];
#pragma unroll
        for (int u = 0; u < 32; u++)
            QP[dh * 32 + u][r_ld] = qv[u];
    }

    float mreg[4] = { -1e30f, -1e30f, -1e30f, -1e30f };
    float kst[32];
    const int key_ld = tid >> 1, dh_ld = tid & 1;

    auto ldg_k = [&](int kt) {
        const float* kp = Kc + (size_t)(kt * 64 + key_ld) * (NKV * HD) + hk * HD + dh_ld * 32;
#pragma unroll
        for (int u = 0; u < 8; u++)
            *(float4*)&kst[u * 4] = ((const float4*)kp)[u];
    };
    auto sts_kT = [&](int buf) {
#pragma unroll
        for (int u = 0; u < 32; u++)
            KV[buf][dh_ld * 32 + u][key_ld] = kst[u];
    };
    auto ldg_v = [&](int kt) {
        const float* vp = Vc + (size_t)(kt * 64 + key_ld) * (NKV * HD) + hk * HD + dh_ld * 32;
#pragma unroll
        for (int u = 0; u < 8; u++)
            *(float4*)&kst[u * 4] = ((const float4*)vp)[u];
    };
    auto sts_v = [&]() {
#pragma unroll
        for (int u = 0; u < 8; u++)
            *(float4*)&KV[0][key_ld][dh_ld * 32 + u * 4] = *(float4*)&kst[u * 4];
    };

    // ================= pass 1: QK GEMM (double-buffered K) ====================
    ldg_k(0);
    sts_kT(0);
    __syncthreads();
    int buf = 0;
    for (int kt = 0; kt <= qtile; kt++) {
        if (kt + 1 <= qtile) ldg_k(kt + 1);

        u64 alo[4][4], ahi[4][4];
#pragma unroll
        for (int a = 0; a < 4; a++)
#pragma unroll
            for (int b = 0; b < 4; b++) { alo[a][b] = 0ull; ahi[a][b] = 0ull; }

#pragma unroll 8
        for (int i = 0; i < 32; i++) {
            float4 qv = *(const float4*)&QP[i][rg * 4];
            double2 ka = *(const double2*)&KV[buf][i][kg * 8];
            double2 kb = *(const double2*)&KV[buf][i][kg * 8 + 4];
            u64 kp_[4] = { d2u(ka.x), d2u(ka.y), d2u(kb.x), d2u(kb.y) };
            u64 q_[4] = { pack2(qv.x, qv.x), pack2(qv.y, qv.y),
                          pack2(qv.z, qv.z), pack2(qv.w, qv.w) };
#pragma unroll
            for (int a = 0; a < 4; a++)
#pragma unroll
                for (int b = 0; b < 4; b++)
                    alo[a][b] = fma2(q_[a], kp_[b], alo[a][b]);
        }
#pragma unroll 8
        for (int i = 32; i < 64; i++) {
            float4 qv = *(const float4*)&QP[i][rg * 4];
            double2 ka = *(const double2*)&KV[buf][i][kg * 8];
            double2 kb = *(const double2*)&KV[buf][i][kg * 8 + 4];
            u64 kp_[4] = { d2u(ka.x), d2u(ka.y), d2u(kb.x), d2u(kb.y) };
            u64 q_[4] = { pack2(qv.x, qv.x), pack2(qv.y, qv.y),
                          pack2(qv.z, qv.z), pack2(qv.w, qv.w) };
#pragma unroll
            for (int a = 0; a < 4; a++)
#pragma unroll
                for (int b = 0; b < 4; b++)
                    ahi[a][b] = fma2(q_[a], kp_[b], ahi[a][b]);
        }

        float scv[8][4];
#pragma unroll
        for (int b = 0; b < 4; b++)
#pragma unroll
            for (int a = 0; a < 4; a++) {
                float l0, l1, h0, h1;
                unpack2(alo[a][b], l0, l1);
                unpack2(ahi[a][b], h0, h1);
                scv[b * 2][a]     = l0 + h0;
                scv[b * 2 + 1][a] = l1 + h1;
            }
#pragma unroll
        for (int jj = 0; jj < 8; jj++) {
            int j = kg * 8 + jj;
            int gj = kt * 64 + j;
            __nv_bfloat162 pa = __floats2bfloat162_rn(scv[jj][0], scv[jj][1]);
            __nv_bfloat162 pb = __floats2bfloat162_rn(scv[jj][2], scv[jj][3]);
            uint2 st;
            st.x = *(unsigned int*)&pa;
            st.y = *(unsigned int*)&pb;
            *(uint2*)(Sc + sbase + (size_t)gj * 64 + rg * 4) = st;
#pragma unroll
            for (int a = 0; a < 4; a++) {
                float s = bf16r(scv[jj][a]) * 0.125f;
                int trow = qtile * 64 + rg * 4 + a;
                if (gj <= trow) mreg[a] = fmaxf(mreg[a], s);
            }
        }

        if (kt + 1 <= qtile) {
            sts_kT(buf ^ 1);     // writes the other buffer; no read conflict
            __syncthreads();
            buf ^= 1;
        }
    }

#pragma unroll
    for (int a = 0; a < 4; a++) {
        float v = mreg[a];
        v = fmaxf(v, __shfl_xor_sync(0xffffffffu, v, 1));
        v = fmaxf(v, __shfl_xor_sync(0xffffffffu, v, 2));
        v = fmaxf(v, __shfl_xor_sync(0xffffffffu, v, 4));
        mreg[a] = v;
    }
    __syncthreads();   // pass-1 KV reads done before pass-3 reuse; m_s below
    if (kg == 0) {
#pragma unroll
        for (int a = 0; a < 4; a++) m_s[rg * 4 + a] = mreg[a];
    }
    __syncthreads();

    // ================= pass 2: l chain (byte-identical structure to R10) =====
    {
        const int r2 = tid >> 1, hf2 = tid & 1;
        const unsigned pair_mask = 0x3u << ((tid & 31) & ~1);
        const float m = m_s[r2];
        float l = 0.0f;
        for (int kt = 0; kt <= qtile; kt++) {
            const int jmax = (kt == qtile) ? r2 : 63;
            int j = 0;
            for (; j + 1 <= jmax; j += 2) {
                int jm = j + hf2;
                float s = __bfloat162float(Sc[sbase + (size_t)(kt * 64 + jm) * 64 + r2]) * 0.125f;
                float e = exp_acc(s - m);
                float eo = __shfl_xor_sync(pair_mask, e, 1);
                float e_even = hf2 ? eo : e;
                float e_odd  = hf2 ? e  : eo;
                l += e_even;
                l += e_odd;
            }
            if (j <= jmax) {
                float s = __bfloat162float(Sc[sbase + (size_t)(kt * 64 + j) * 64 + r2]) * 0.125f;
                l += exp_acc(s - m);
            }
        }
        if (hf2 == 0) l_s[r2] = l;
    }
    __syncthreads();

    // ================= pass 3: probs (PsT[j][row]) + PV GEMM =================
    u64 o2[4][4];
#pragma unroll
    for (int a = 0; a < 4; a++)
#pragma unroll
        for (int b = 0; b < 4; b++) o2[a][b] = 0ull;

    const int pj = tid & 63, ph = tid >> 6;

    ldg_v(0);
    for (int kt = 0; kt <= qtile; kt++) {
        __syncthreads();
        sts_v();
        {
            const unsigned int* spw = (const unsigned int*)
                (Sc + sbase + (size_t)(kt * 64 + pj) * 64 + ph * 32);
            const int gj = kt * 64 + pj;
#pragma unroll
            for (int q4 = 0; q4 < 4; q4++) {
                uint4 wv = ((const uint4*)spw)[q4];
                unsigned int ws[4] = { wv.x, wv.y, wv.z, wv.w };
                float pv[8];
#pragma unroll
                for (int wi = 0; wi < 4; wi++) {
                    unsigned int word = ws[wi];
                    int rr0 = wi * 2;
#pragma unroll
                    for (int e = 0; e < 2; e++) {
                        int row = ph * 32 + q4 * 8 + rr0 + e;
                        float p = 0.0f;
                        if (gj <= qtile * 64 + row) {
                            float sv = __uint_as_float(e ? (word & 0xffff0000u)
                                                         : (word << 16));
                            float s = sv * 0.125f;
                            p = bf16r(__fdiv_rn(exp_acc(s - m_s[row]), l_s[row]));
                        }
                        pv[rr0 + e] = p;
                    }
                }
                *(float4*)&QP[pj][ph * 32 + q4 * 8]     = *(float4*)&pv[0];
                *(float4*)&QP[pj][ph * 32 + q4 * 8 + 4] = *(float4*)&pv[4];
            }
        }
        __syncthreads();
        if (kt + 1 <= qtile) ldg_v(kt + 1);

#pragma unroll 2
        for (int j = 0; j < 64; j++) {
            float4 pf = *(const float4*)&QP[j][rg * 4];
            u64 pp[4] = { pack2(pf.x, pf.x), pack2(pf.y, pf.y),
                          pack2(pf.z, pf.z), pack2(pf.w, pf.w) };
            double2 va = *(const double2*)&KV[0][j][kg * 8];
            double2 vb = *(const double2*)&KV[0][j][kg * 8 + 4];
            u64 vv[4] = { d2u(va.x), d2u(va.y), d2u(vb.x), d2u(vb.y) };
#pragma unroll
            for (int a = 0; a < 4; a++)
#pragma unroll
                for (int b = 0; b < 4; b++)
                    o2[a][b] = fma2(pp[a], vv[b], o2[a][b]);
        }
    }

#pragma unroll
    for (int a = 0; a < 4; a++) {
        int trow = qtile * 64 + rg * 4 + a;
        float* op = O + (size_t)trow * D_MODEL + h * HD + kg * 8;
        float f0, f1, f2, f3, f4, f5, f6, f7;
        unpack2(o2[a][0], f0, f1);
        unpack2(o2[a][1], f2, f3);
        unpack2(o2[a][2], f4, f5);
        unpack2(o2[a][3], f6, f7);
        *(float4*)&op[0] = make_float4(bf16r(f0), bf16r(f1), bf16r(f2), bf16r(f3));
        *(float4*)&op[4] = make_float4(bf16r(f4), bf16r(f5), bf16r(f6), bf16r(f7));
    }
}

// ---------------- host launcher ----------------------------------------------
extern "C" void kernel_launch(void* const* d_in, const int* in_sizes, int n_in,
                              void* d_out, int out_size) {
    (void)out_size;

    const float *x = 0, *w_o = 0, *scale_q = 0, *scale_kv = 0;
    const float *p524[2] = {0, 0}, *p262[3] = {0, 0, 0}, *p65[2] = {0, 0};
    int n524 = 0, n262 = 0, n65 = 0;
    for (int i = 0; i < n_in; i++) {
        switch (in_sizes[i]) {
            case 4194304: x = (const float*)d_in[i]; break;
            case 1048576: w_o = (const float*)d_in[i]; break;
            case 512:     scale_q  = (const float*)d_in[i]; break;
            case 256:     scale_kv = (const float*)d_in[i]; break;
            case 524288:  if (n524 < 2) p524[n524++] = (const float*)d_in[i]; break;
            case 262144:  if (n262 < 3) p262[n262++] = (const float*)d_in[i]; break;
            case 65536:   if (n65 < 2)  p65[n65++]  = (const float*)d_in[i]; break;
            default: break;
        }
    }
    const float* w_dq  = p524[0];
    const float* w_uq  = p524[1];
    const float* sin_p = p262[0];
    const float* cos_p = p262[1];
    const float* w_dkv = p262[2];
    const float* w_uk  = p65[0];
    const float* w_uv  = p65[1];
    float* out = (float*)d_out;

    float *qlat_raw, *qlat, *q_ro, *kvraw, *kvlat, *k_ro, *vb, *attn;
    __nv_bfloat16* scores;
    cudaGetSymbolAddress((void**)&qlat_raw, g_qlat_raw);
    cudaGetSymbolAddress((void**)&qlat,     g_qlat);
    cudaGetSymbolAddress((void**)&q_ro,     g_q_ro);
    cudaGetSymbolAddress((void**)&kvraw,    g_kvraw);
    cudaGetSymbolAddress((void**)&kvlat,    g_kvlat);
    cudaGetSymbolAddress((void**)&k_ro,     g_k_ro);
    cudaGetSymbolAddress((void**)&vb,       g_v);
    cudaGetSymbolAddress((void**)&attn,     g_attn);
    cudaGetSymbolAddress((void**)&scores,   g_scores);

    // launch 0: both down-projections
    downproj_kernel<<<768, 128>>>(x, w_dq, qlat_raw, w_dkv, kvraw);
    // launch 1: both rmsnorms
    rmsnorm_both<<<dim3(T_SEQ, 2), 256>>>(qlat_raw, scale_q, qlat,
                                          kvraw, scale_kv, kvlat);
    // launch 2: up-projections + fused rope (q,k), v plain
    gemm3_rope_kernel<<<1536, 128>>>(qlat, w_uq, q_ro, kvlat, w_uk, k_ro,
                                     w_uv, vb, sin_p, cos_p);
    // launch 3: attention  <-- ncu (-s 5 counts 2 harness launches first)
    attn_kernel<<<dim3(T_SEQ / 64, NH), 128>>>(q_ro, k_ro, vb, attn, scores);
    // launch 4: final projection
    gemm_wo_kernel<<<dim3(D_MODEL / 64, T_SEQ / 64), 128>>>(attn, w_o, out);
}

// round 16
// speedup vs baseline: 1.0953x; 1.0880x over previous
#include <cuda_runtime.h>
#include <cuda_bf16.h>
#include <cstdint>

#define T_SEQ   4096
#define D_MODEL 1024
#define NH      16
#define NKV     4
#define HD      64
#define QL      512
#define KVL     256
#define TRI_ENT 8519680                 // 2080 tile-pairs * 4096 entries per head

// ---------------- scratch (device globals; all f32, values bf16-rounded) -----
static __device__ float g_qlat_raw[T_SEQ * QL];
static __device__ float g_qlat    [T_SEQ * QL];
static __device__ float g_q_ro    [T_SEQ * NH * HD];
static __device__ float g_kvraw   [T_SEQ * KVL];
static __device__ float g_kvlat   [T_SEQ * KVL];
static __device__ float g_k_ro    [T_SEQ * NKV * HD];
static __device__ float g_v       [T_SEQ * NKV * HD];
static __device__ float g_attn    [T_SEQ * D_MODEL];

static __device__ __nv_bfloat16 g_scores[(size_t)NH * TRI_ENT];

// ---------------- helpers -----------------------------------------------------
__device__ __forceinline__ float bf16r(float x) {
    return __bfloat162float(__float2bfloat16(x));
}

typedef unsigned long long u64;

__device__ __forceinline__ u64 pack2(float lo, float hi) {
    u64 r;
    asm("mov.b64 %0, {%1, %2};" : "=l"(r) : "f"(lo), "f"(hi));
    return r;
}
__device__ __forceinline__ void unpack2(u64 v, float& lo, float& hi) {
    asm("mov.b64 {%0, %1}, %2;" : "=f"(lo), "=f"(hi) : "l"(v));
}
__device__ __forceinline__ u64 d2u(double d) {
    return (u64)__double_as_longlong(d);
}
__device__ __forceinline__ u64 fma2(u64 a, u64 b, u64 c) {
    u64 d;
    asm("fma.rn.f32x2 %0, %1, %2, %3;" : "=l"(d) : "l"(a), "l"(b), "l"(c));
    return d;
}

// Deterministic ~1-ulp exp, fmaf-only (identical since round 7).
__device__ __forceinline__ float exp_acc(float x) {
    x = fmaxf(x, -87.0f);
    float n = rintf(x * 1.44269504088896340736f);
    float r = fmaf(n, -0.693145751953125f, x);
    r = fmaf(n, -1.42860677e-06f, r);
    float p = 1.9841269841e-04f;
    p = fmaf(p, r, 1.3888888889e-03f);
    p = fmaf(p, r, 8.3333333333e-03f);
    p = fmaf(p, r, 4.1666666667e-02f);
    p = fmaf(p, r, 1.6666666667e-01f);
    p = fmaf(p, r, 0.5f);
    p = fmaf(p, r, 1.0f);
    p = fmaf(p, r, 1.0f);
    int in = (int)n;
    return p * __int_as_float((in + 127) << 23);
}

// ---------------- GEMM body: 64x64 tile, BK=32, FFMA2 + prefetch --------------
// rope=1: apply RoPE to the bf16r outputs in the epilogue (tile == one head).
__device__ __forceinline__ void gemm_body(const float* __restrict__ A,
                                          const float* __restrict__ B,
                                          float* __restrict__ C,
                                          int N, int K, int row0, int col0,
                                          float (*As)[68], float (*Bs)[68],
                                          const float* __restrict__ sin_t,
                                          const float* __restrict__ cos_t,
                                          int rope) {
    const int tid = threadIdx.x;
    const int tx = tid & 15;
    const int ty = tid >> 4;

    const int a_row  = tid & 63;
    const int a_half = tid >> 6;
    const int b_row  = tid >> 2;
    const int b_col  = (tid & 3) * 16;

    const int nkt = K >> 5;
    float a_st[16], b_st[16];

    auto ldg_tile = [&](int kt) {
        const float* ap = A + (size_t)(row0 + a_row) * K + kt * 32 + a_half * 16;
#pragma unroll
        for (int u = 0; u < 4; u++)
            *(float4*)&a_st[u * 4] = ((const float4*)ap)[u];
        const float* bp = B + (size_t)(kt * 32 + b_row) * N + col0 + b_col;
#pragma unroll
        for (int u = 0; u < 4; u++)
            *(float4*)&b_st[u * 4] = ((const float4*)bp)[u];
    };
    auto sts_tile = [&]() {
#pragma unroll
        for (int u = 0; u < 16; u++)
            As[a_half * 16 + u][a_row] = a_st[u];
#pragma unroll
        for (int u = 0; u < 4; u++)
            *(float4*)&Bs[b_row][b_col + u * 4] = *(float4*)&b_st[u * 4];
    };

    u64 acc2[4][4];
#pragma unroll
    for (int p = 0; p < 4; p++)
#pragma unroll
        for (int j = 0; j < 4; j++) acc2[p][j] = 0ull;

    ldg_tile(0);
    sts_tile();
    __syncthreads();

    for (int kt = 0; kt < nkt; kt++) {
        if (kt + 1 < nkt) ldg_tile(kt + 1);

#pragma unroll 4
        for (int kk = 0; kk < 32; kk++) {
            float4 bf = *(const float4*)&Bs[kk][tx * 4];
            u64 b0 = pack2(bf.x, bf.x);
            u64 b1 = pack2(bf.y, bf.y);
            u64 b2 = pack2(bf.z, bf.z);
            u64 b3 = pack2(bf.w, bf.w);
            double2 a01 = *(const double2*)&As[kk][ty * 8];
            double2 a23 = *(const double2*)&As[kk][ty * 8 + 4];
            u64 ap_[4] = { d2u(a01.x), d2u(a01.y), d2u(a23.x), d2u(a23.y) };
#pragma unroll
            for (int p = 0; p < 4; p++) {
                acc2[p][0] = fma2(ap_[p], b0, acc2[p][0]);
                acc2[p][1] = fma2(ap_[p], b1, acc2[p][1]);
                acc2[p][2] = fma2(ap_[p], b2, acc2[p][2]);
                acc2[p][3] = fma2(ap_[p], b3, acc2[p][3]);
            }
        }

        if (kt + 1 < nkt) {
            __syncthreads();
            sts_tile();
            __syncthreads();
        }
    }

#pragma unroll
    for (int p = 0; p < 4; p++) {
        float ve[4], vo[4];
        unpack2(acc2[p][0], ve[0], vo[0]);
        unpack2(acc2[p][1], ve[1], vo[1]);
        unpack2(acc2[p][2], ve[2], vo[2]);
        unpack2(acc2[p][3], ve[3], vo[3]);
#pragma unroll
        for (int i = 0; i < 4; i++) { ve[i] = bf16r(ve[i]); vo[i] = bf16r(vo[i]); }

        if (rope) {
            const int te = row0 + ty * 8 + 2 * p;
            const int to = te + 1;
            float oe[4], oo[4];
#pragma unroll
            for (int i = 0; i < 4; i++) {
                float pe = __shfl_xor_sync(0xffffffffu, ve[i], 8);
                float po = __shfl_xor_sync(0xffffffffu, vo[i], 8);
                int d = tx * 4 + i;
                float re = (d < 32) ? -pe : pe;
                float ro = (d < 32) ? -po : po;
                float ce = cos_t[te * HD + d], se = sin_t[te * HD + d];
                float co = cos_t[to * HD + d], so = sin_t[to * HD + d];
                oe[i] = bf16r(bf16r(ve[i] * ce) + bf16r(re * se));
                oo[i] = bf16r(bf16r(vo[i] * co) + bf16r(ro * so));
            }
#pragma unroll
            for (int i = 0; i < 4; i++) { ve[i] = oe[i]; vo[i] = oo[i]; }
        }

        *(float4*)&C[(size_t)(row0 + ty * 8 + 2 * p)     * N + col0 + tx * 4] =
            make_float4(ve[0], ve[1], ve[2], ve[3]);
        *(float4*)&C[(size_t)(row0 + ty * 8 + 2 * p + 1) * N + col0 + tx * 4] =
            make_float4(vo[0], vo[1], vo[2], vo[3]);
    }
}

// launch 0: both down-projections
__global__ void __launch_bounds__(128, 4)
downproj_kernel(const float* __restrict__ x,
                const float* __restrict__ w_dq, float* __restrict__ qlat_raw,
                const float* __restrict__ w_dkv, float* __restrict__ kvraw) {
    __shared__ float As[32][68];
    __shared__ float Bs[32][68];
    int bx = blockIdx.x;
    if (bx < 512)
        gemm_body(x, w_dq, qlat_raw, QL, D_MODEL, (bx >> 3) * 64, (bx & 7) * 64,
                  As, Bs, 0, 0, 0);
    else {
        int b = bx - 512;
        gemm_body(x, w_dkv, kvraw, KVL, D_MODEL, (b >> 2) * 64, (b & 3) * 64,
                  As, Bs, 0, 0, 0);
    }
}

// launch 2: q/k up-projections WITH fused rope, v plain
__global__ void __launch_bounds__(128, 4)
gemm3_rope_kernel(const float* __restrict__ qlat, const float* __restrict__ w_uq,
                  float* __restrict__ q_ro,
                  const float* __restrict__ kvlat, const float* __restrict__ w_uk,
                  float* __restrict__ k_ro, const float* __restrict__ w_uv,
                  float* __restrict__ vb,
                  const float* __restrict__ sin_t,
                  const float* __restrict__ cos_t) {
    __shared__ float As[32][68];
    __shared__ float Bs[32][68];
    int bx = blockIdx.x;
    if (bx < 1024) {
        gemm_body(qlat, w_uq, q_ro, NH * HD, QL, (bx >> 4) * 64, (bx & 15) * 64,
                  As, Bs, sin_t, cos_t, 1);
    } else if (bx < 1280) {
        int b = bx - 1024;
        gemm_body(kvlat, w_uk, k_ro, NKV * HD, KVL, (b >> 2) * 64, (b & 3) * 64,
                  As, Bs, sin_t, cos_t, 1);
    } else {
        int b = bx - 1280;
        gemm_body(kvlat, w_uv, vb, NKV * HD, KVL, (b >> 2) * 64, (b & 3) * 64,
                  As, Bs, 0, 0, 0);
    }
}

// launch 4: final projection
__global__ void __launch_bounds__(128, 4)
gemm_wo_kernel(const float* __restrict__ A,
               const float* __restrict__ B,
               float* __restrict__ C) {
    __shared__ float As[32][68];
    __shared__ float Bs[32][68];
    gemm_body(A, B, C, D_MODEL, D_MODEL, blockIdx.y * 64, blockIdx.x * 64,
              As, Bs, 0, 0, 0);
}

// ---------------- RMSNorm merged (same FP ops per row) -------------------------
__global__ void rmsnorm_both(const float* __restrict__ inq,
                             const float* __restrict__ scq,
                             float* __restrict__ outq,
                             const float* __restrict__ inkv,
                             const float* __restrict__ sckv,
                             float* __restrict__ outkv) {
    const float* in;
    const float* scale;
    float* out;
    int cols;
    if (blockIdx.y == 0) { in = inq;  scale = scq;  out = outq;  cols = QL;  }
    else                 { in = inkv; scale = sckv; out = outkv; cols = KVL; }

    const int row = blockIdx.x;
    const int tid = threadIdx.x;
    const float* x = in + (size_t)row * cols;
    float* y = out + (size_t)row * cols;

    __shared__ float red[256];
    float s = 0.0f;
    for (int c = tid; c < cols; c += 256) {
        float v = x[c];
        s = fmaf(v, v, s);
    }
    red[tid] = s;
    __syncthreads();
    for (int off = 128; off > 0; off >>= 1) {
        if (tid < off) red[tid] += red[tid + off];
        __syncthreads();
    }
    float rms = __fsqrt_rn(red[0] / (float)cols + 1e-6f);
    for (int c = tid; c < cols; c += 256)
        y[c] = bf16r(__fdiv_rn(x[c], rms) * scale[c]);
}

// ---------------- causal attention: single-buffer, occupancy 5 ----------------
// FP values/order identical to R10-R15.
__global__ void __launch_bounds__(128, 5)
attn_kernel(const float* __restrict__ Q,
            const float* __restrict__ Kc,
            const float* __restrict__ Vc,
            float* __restrict__ O,
            __nv_bfloat16* __restrict__ Sc) {
    __shared__ float QP[64][68];   // pass1: Qs[i][row]; pass3: PsT[j][row]
    __shared__ float KV[64][68];   // pass1: Ks[i][key]; pass3: Vs[j][dim]
    __shared__ float m_s[64];
    __shared__ float l_s[64];

    const int qtile = (int)gridDim.x - 1 - (int)blockIdx.x;
    const int h = blockIdx.y;
    const int hk = h >> 2;
    const int tid = threadIdx.x;
    const size_t sbase = (size_t)h * TRI_ENT +
                         (size_t)qtile * (qtile + 1) / 2 * 4096;

    const int rg = tid >> 3;
    const int kg = tid & 7;

    {
        const int r_ld = tid >> 1, dh = tid & 1;
        const float* qp = Q + (size_t)(qtile * 64 + r_ld) * D_MODEL + h * HD + dh * 32;
        float qv[32];
#pragma unroll
        for (int u = 0; u < 8; u++)
            *(float4*)&qv[u * 4] = ((const float4*)qp)[u];
#pragma unroll
        for (int u = 0; u < 32; u++)
            QP[dh * 32 + u][r_ld] = qv[u];
    }

    float mreg[4] = { -1e30f, -1e30f, -1e30f, -1e30f };
    const int key_ld = tid >> 1, dh_ld = tid & 1;

    // ================= pass 1: QK GEMM, store bf16 scores, exact max =========
    for (int kt = 0; kt <= qtile; kt++) {
        __syncthreads();
        {
            const float* kp = Kc + (size_t)(kt * 64 + key_ld) * (NKV * HD) + hk * HD + dh_ld * 32;
            float kv[32];
#pragma unroll
            for (int u = 0; u < 8; u++)
                *(float4*)&kv[u * 4] = ((const float4*)kp)[u];
#pragma unroll
            for (int u = 0; u < 32; u++)
                KV[dh_ld * 32 + u][key_ld] = kv[u];
        }
        __syncthreads();

        u64 alo[4][4], ahi[4][4];
#pragma unroll
        for (int a = 0; a < 4; a++)
#pragma unroll
            for (int b = 0; b < 4; b++) { alo[a][b] = 0ull; ahi[a][b] = 0ull; }

#pragma unroll 8
        for (int i = 0; i < 32; i++) {
            float4 qv = *(const float4*)&QP[i][rg * 4];
            double2 ka = *(const double2*)&KV[i][kg * 8];
            double2 kb = *(const double2*)&KV[i][kg * 8 + 4];
            u64 kp_[4] = { d2u(ka.x), d2u(ka.y), d2u(kb.x), d2u(kb.y) };
            u64 q_[4] = { pack2(qv.x, qv.x), pack2(qv.y, qv.y),
                          pack2(qv.z, qv.z), pack2(qv.w, qv.w) };
#pragma unroll
            for (int a = 0; a < 4; a++)
#pragma unroll
                for (int b = 0; b < 4; b++)
                    alo[a][b] = fma2(q_[a], kp_[b], alo[a][b]);
        }
#pragma unroll 8
        for (int i = 32; i < 64; i++) {
            float4 qv = *(const float4*)&QP[i][rg * 4];
            double2 ka = *(const double2*)&KV[i][kg * 8];
            double2 kb = *(const double2*)&KV[i][kg * 8 + 4];
            u64 kp_[4] = { d2u(ka.x), d2u(ka.y), d2u(kb.x), d2u(kb.y) };
            u64 q_[4] = { pack2(qv.x, qv.x), pack2(qv.y, qv.y),
                          pack2(qv.z, qv.z), pack2(qv.w, qv.w) };
#pragma unroll
            for (int a = 0; a < 4; a++)
#pragma unroll
                for (int b = 0; b < 4; b++)
                    ahi[a][b] = fma2(q_[a], kp_[b], ahi[a][b]);
        }

        float scv[8][4];
#pragma unroll
        for (int b = 0; b < 4; b++)
#pragma unroll
            for (int a = 0; a < 4; a++) {
                float l0, l1, h0, h1;
                unpack2(alo[a][b], l0, l1);
                unpack2(ahi[a][b], h0, h1);
                scv[b * 2][a]     = l0 + h0;
                scv[b * 2 + 1][a] = l1 + h1;
            }
#pragma unroll
        for (int jj = 0; jj < 8; jj++) {
            int j = kg * 8 + jj;
            int gj = kt * 64 + j;
            __nv_bfloat162 pa = __floats2bfloat162_rn(scv[jj][0], scv[jj][1]);
            __nv_bfloat162 pb = __floats2bfloat162_rn(scv[jj][2], scv[jj][3]);
            uint2 st;
            st.x = *(unsigned int*)&pa;
            st.y = *(unsigned int*)&pb;
            *(uint2*)(Sc + sbase + (size_t)gj * 64 + rg * 4) = st;
#pragma unroll
            for (int a = 0; a < 4; a++) {
                float s = bf16r(scv[jj][a]) * 0.125f;
                int trow = qtile * 64 + rg * 4 + a;
                if (gj <= trow) mreg[a] = fmaxf(mreg[a], s);
            }
        }
    }

#pragma unroll
    for (int a = 0; a < 4; a++) {
        float v = mreg[a];
        v = fmaxf(v, __shfl_xor_sync(0xffffffffu, v, 1));
        v = fmaxf(v, __shfl_xor_sync(0xffffffffu, v, 2));
        v = fmaxf(v, __shfl_xor_sync(0xffffffffu, v, 4));
        mreg[a] = v;
    }
    if (kg == 0) {
#pragma unroll
        for (int a = 0; a < 4; a++) m_s[rg * 4 + a] = mreg[a];
    }
    __syncthreads();

    // ================= pass 2: l chain (byte-identical structure to R10) =====
    {
        const int r2 = tid >> 1, hf2 = tid & 1;
        const unsigned pair_mask = 0x3u << ((tid & 31) & ~1);
        const float m = m_s[r2];
        float l = 0.0f;
        for (int kt = 0; kt <= qtile; kt++) {
            const int jmax = (kt == qtile) ? r2 : 63;
            int j = 0;
            for (; j + 1 <= jmax; j += 2) {
                int jm = j + hf2;
                float s = __bfloat162float(Sc[sbase + (size_t)(kt * 64 + jm) * 64 + r2]) * 0.125f;
                float e = exp_acc(s - m);
                float eo = __shfl_xor_sync(pair_mask, e, 1);
                float e_even = hf2 ? eo : e;
                float e_odd  = hf2 ? e  : eo;
                l += e_even;
                l += e_odd;
            }
            if (j <= jmax) {
                float s = __bfloat162float(Sc[sbase + (size_t)(kt * 64 + j) * 64 + r2]) * 0.125f;
                l += exp_acc(s - m);
            }
        }
        if (hf2 == 0) l_s[r2] = l;
    }
    __syncthreads();

    // ================= pass 3: probs (PsT[j][row]) + PV GEMM =================
    u64 o2[4][4];
#pragma unroll
    for (int a = 0; a < 4; a++)
#pragma unroll
        for (int b = 0; b < 4; b++) o2[a][b] = 0ull;

    const int pj = tid & 63, ph = tid >> 6;

    for (int kt = 0; kt <= qtile; kt++) {
        __syncthreads();
        {
            const float* vp = Vc + (size_t)(kt * 64 + key_ld) * (NKV * HD) + hk * HD + dh_ld * 32;
#pragma unroll
            for (int u = 0; u < 8; u++)
                *(float4*)&KV[key_ld][dh_ld * 32 + u * 4] = ((const float4*)vp)[u];
        }
        {
            const unsigned int* spw = (const unsigned int*)
                (Sc + sbase + (size_t)(kt * 64 + pj) * 64 + ph * 32);
            const int gj = kt * 64 + pj;
#pragma unroll
            for (int q4 = 0; q4 < 4; q4++) {
                uint4 wv = ((const uint4*)spw)[q4];
                unsigned int ws[4] = { wv.x, wv.y, wv.z, wv.w };
                float pv[8];
#pragma unroll
                for (int wi = 0; wi < 4; wi++) {
                    unsigned int word = ws[wi];
                    int rr0 = wi * 2;
#pragma unroll
                    for (int e = 0; e < 2; e++) {
                        int row = ph * 32 + q4 * 8 + rr0 + e;
                        float p = 0.0f;
                        if (gj <= qtile * 64 + row) {
                            float sv = __uint_as_float(e ? (word & 0xffff0000u)
                                                         : (word << 16));
                            float s = sv * 0.125f;
                            p = bf16r(__fdiv_rn(exp_acc(s - m_s[row]), l_s[row]));
                        }
                        pv[rr0 + e] = p;
                    }
                }
                *(float4*)&QP[pj][ph * 32 + q4 * 8]     = *(float4*)&pv[0];
                *(float4*)&QP[pj][ph * 32 + q4 * 8 + 4] = *(float4*)&pv[4];
            }
        }
        __syncthreads();

#pragma unroll 2
        for (int j = 0; j < 64; j++) {
            float4 pf = *(const float4*)&QP[j][rg * 4];
            u64 pp[4] = { pack2(pf.x, pf.x), pack2(pf.y, pf.y),
                          pack2(pf.z, pf.z), pack2(pf.w, pf.w) };
            double2 va = *(const double2*)&KV[j][kg * 8];
            double2 vb = *(const double2*)&KV[j][kg * 8 + 4];
            u64 vv[4] = { d2u(va.x), d2u(va.y), d2u(vb.x), d2u(vb.y) };
#pragma unroll
            for (int a = 0; a < 4; a++)
#pragma unroll
                for (int b = 0; b < 4; b++)
                    o2[a][b] = fma2(pp[a], vv[b], o2[a][b]);
        }
    }

#pragma unroll
    for (int a = 0; a < 4; a++) {
        int trow = qtile * 64 + rg * 4 + a;
        float* op = O + (size_t)trow * D_MODEL + h * HD + kg * 8;
        float f0, f1, f2, f3, f4, f5, f6, f7;
        unpack2(o2[a][0], f0, f1);
        unpack2(o2[a][1], f2, f3);
        unpack2(o2[a][2], f4, f5);
        unpack2(o2[a][3], f6, f7);
        *(float4*)&op[0] = make_float4(bf16r(f0), bf16r(f1), bf16r(f2), bf16r(f3));
        *(float4*)&op[4] = make_float4(bf16r(f4), bf16r(f5), bf16r(f6), bf16r(f7));
    }
}

// ---------------- host launcher ----------------------------------------------
extern "C" void kernel_launch(void* const* d_in, const int* in_sizes, int n_in,
                              void* d_out, int out_size) {
    (void)out_size;

    const float *x = 0, *w_o = 0, *scale_q = 0, *scale_kv = 0;
    const float *p524[2] = {0, 0}, *p262[3] = {0, 0, 0}, *p65[2] = {0, 0};
    int n524 = 0, n262 = 0, n65 = 0;
    for (int i = 0; i < n_in; i++) {
        switch (in_sizes[i]) {
            case 4194304: x = (const float*)d_in[i]; break;
            case 1048576: w_o = (const float*)d_in[i]; break;
            case 512:     scale_q  = (const float*)d_in[i]; break;
            case 256:     scale_kv = (const float*)d_in[i]; break;
            case 524288:  if (n524 < 2) p524[n524++] = (const float*)d_in[i]; break;
            case 262144:  if (n262 < 3) p262[n262++] = (const float*)d_in[i]; break;
            case 65536:   if (n65 < 2)  p65[n65++]  = (const float*)d_in[i]; break;
            default: break;
        }
    }
    const float* w_dq  = p524[0];
    const float* w_uq  = p524[1];
    const float* sin_p = p262[0];
    const float* cos_p = p262[1];
    const float* w_dkv = p262[2];
    const float* w_uk  = p65[0];
    const float* w_uv  = p65[1];
    float* out = (float*)d_out;

    float *qlat_raw, *qlat, *q_ro, *kvraw, *kvlat, *k_ro, *vb, *attn;
    __nv_bfloat16* scores;
    cudaGetSymbolAddress((void**)&qlat_raw, g_qlat_raw);
    cudaGetSymbolAddress((void**)&qlat,     g_qlat);
    cudaGetSymbolAddress((void**)&q_ro,     g_q_ro);
    cudaGetSymbolAddress((void**)&kvraw,    g_kvraw);
    cudaGetSymbolAddress((void**)&kvlat,    g_kvlat);
    cudaGetSymbolAddress((void**)&k_ro,     g_k_ro);
    cudaGetSymbolAddress((void**)&vb,       g_v);
    cudaGetSymbolAddress((void**)&attn,     g_attn);
    cudaGetSymbolAddress((void**)&scores,   g_scores);

    // launch 0: both down-projections
    downproj_kernel<<<768, 128>>>(x, w_dq, qlat_raw, w_dkv, kvraw);
    // launch 1: both rmsnorms
    rmsnorm_both<<<dim3(T_SEQ, 2), 256>>>(qlat_raw, scale_q, qlat,
                                          kvraw, scale_kv, kvlat);
    // launch 2: up-projections + fused rope (q,k), v plain
    gemm3_rope_kernel<<<1536, 128>>>(qlat, w_uq, q_ro, kvlat, w_uk, k_ro,
                                     w_uv, vb, sin_p, cos_p);
    // launch 3: attention  <-- profiled by ncu (-s 5: 2 harness launches first)
    attn_kernel<<<dim3(T_SEQ / 64, NH), 128>>>(q_ro, k_ro, vb, attn, scores);
    // launch 4: final projection
    gemm_wo_kernel<<<dim3(D_MODEL / 64, T_SEQ / 64), 128>>>(attn, w_o, out);
}